// round 15
// baseline (speedup 1.0000x reference)
#include <cuda_runtime.h>
#include <cuda_fp16.h>
#include <cstdint>

#define Nn 100000
#define Ee 1600000
#define Dd 128
#define Hh 8
#define FF 512

// ---------------- scratch (device globals; no allocs allowed) ----------------
__device__ float g_h[Nn * Dd];        // LN1 output (fp32, for rst)
__device__ float g_feat0[Nn * Dd];    // GEMM1 out (fp32); later rst
__device__ float g_eh[Nn * Hh];
__device__ float g_et[Nn * Hh];
__device__ float g_invs[Nn * Hh];     // per-(node,head) 1/sum(exp)
__device__ int   g_srccsr[Ee];        // src node per CSR slot
__device__ int   g_cnt[Nn];
__device__ int   g_rowptr[Nn + 1];
__device__ int   g_wptr[Nn];
__device__ int   g_bsum[128];
// half-precision operands
__device__ __align__(256) __half g_ach[Ee * Hh];   // UNNORMALIZED exp(e) (half)
__device__ __align__(256) __half g_hA[Nn * Dd];    // half(h)  (GEMM1 A)
__device__ __align__(256) __half g_xh[Nn * Dd];    // half(x)  (FFN1 A)
__device__ __align__(256) __half g_hid[Nn * FF];   // half(hidden) (FFN2 A)
__device__ __align__(256) __half g_f0h[Nn * Dd];   // half(feat0) residual
__device__ __align__(256) __half g_hw0[Dd * Dd];
__device__ __align__(256) __half g_hw1[FF * Dd];
__device__ __align__(256) __half g_hw2[Dd * FF];
__device__ __align__(256) __half g_pA[Nn * Dd];    // hop ping (half)
__device__ __align__(256) __half g_pB[Nn * Dd];    // hop pong (half)

__device__ __forceinline__ float* gbuf(int i) {
    switch (i) {
        case 0: return g_h;
        case 1: return g_feat0;
    }
    return nullptr;
}
__device__ __forceinline__ const __half* hbuf(int i) {
    switch (i) {
        case 0: return g_hA;
        case 1: return g_xh;
        case 2: return g_hid;
        case 3: return g_hw0;
        case 4: return g_hw1;
        case 5: return g_hw2;
        case 6: return g_pA;
        case 7: return g_pB;
    }
    return nullptr;
}
__device__ __forceinline__ __half* hbufw(int i) {
    switch (i) {
        case 6: return g_pA;
        case 7: return g_pB;
    }
    return nullptr;
}

__device__ __forceinline__ void mma_f16(float& c0, float& c1, float& c2, float& c3,
                                        uint32_t a0, uint32_t a1, uint32_t a2, uint32_t a3,
                                        uint32_t b0, uint32_t b1) {
    asm volatile(
        "mma.sync.aligned.m16n8k16.row.col.f32.f16.f16.f32 "
        "{%0,%1,%2,%3}, {%4,%5,%6,%7}, {%8,%9}, {%0,%1,%2,%3};"
        : "+f"(c0), "+f"(c1), "+f"(c2), "+f"(c3)
        : "r"(a0), "r"(a1), "r"(a2), "r"(a3), "r"(b0), "r"(b1));
}

__device__ __forceinline__ void cpasync16(uint32_t s, const void* g, int sz) {
    asm volatile("cp.async.cg.shared.global [%0], [%1], 16, %2;"
                 :: "r"(s), "l"(g), "r"(sz) : "memory");
}
#define CP_COMMIT() asm volatile("cp.async.commit_group;" ::: "memory")
#define CP_WAIT1() asm volatile("cp.async.wait_group 1;" ::: "memory")
#define CP_WAIT0() asm volatile("cp.async.wait_group 0;" ::: "memory")

#define RS 40   // smem row stride in halves (80 B: 16B-aligned, bank-spread)

// ---------------- fp16 mma GEMM + cp.async double buffer ----------------
// mode 0: fp32 C + half copies to g_pA/g_f0h   mode 1: half(relu(x+bias)) -> g_hid
// mode 2: fp32 x + bias + add
__global__ void __launch_bounds__(256, 2) hgemm_kernel(int Ai, int Bi,
                                                       const float* __restrict__ bias,
                                                       int Addi, int Ci, float* __restrict__ Cext,
                                                       int M, int K, int mode) {
    __shared__ __half As[2][128 * RS];
    __shared__ __half Bs[2][128 * RS];
    const __half* A = hbuf(Ai);
    const __half* B = hbuf(Bi);
    float* C = (Ci >= 0) ? gbuf(Ci) : Cext;
    const float* add = (Addi >= 0) ? gbuf(Addi) : nullptr;

    int bm = blockIdx.y * 128;
    int bn = blockIdx.x * 128;
    int tid = threadIdx.x;
    int wid = tid >> 5, lane = tid & 31;
    int g = lane >> 2, t4 = lane & 3;
    int warpM = wid & 3, warpN = wid >> 2;

    float acc[2][8][4];
    #pragma unroll
    for (int i = 0; i < 2; i++)
        #pragma unroll
        for (int j = 0; j < 8; j++)
            #pragma unroll
            for (int q = 0; q < 4; q++) acc[i][j][q] = 0.0f;

    int crow = tid >> 1;
    int cch = (tid & 1) * 2;
    bool aval = (bm + crow) < Nn;
    const __half* agp = A + (size_t)(aval ? (bm + crow) : 0) * K + cch * 8;
    const __half* bgp = B + (size_t)(bn + crow) * K + cch * 8;
    int asz = aval ? 16 : 0;

    uint32_t sA = (uint32_t)__cvta_generic_to_shared(As);
    uint32_t sB = (uint32_t)__cvta_generic_to_shared(Bs);
    uint32_t dA = sA + (uint32_t)(crow * RS + cch * 8) * 2u;
    uint32_t dB = sB + (uint32_t)(crow * RS + cch * 8) * 2u;
    const uint32_t BUFB = 128 * RS * 2;

    const int nit = K >> 5;
    {
        cpasync16(dA, agp, asz);
        cpasync16(dA + 16, agp + 8, asz);
        cpasync16(dB, bgp, 16);
        cpasync16(dB + 16, bgp + 8, 16);
        CP_COMMIT();
    }

    for (int i = 0; i < nit; i++) {
        if (i + 1 < nit) {
            uint32_t boff = ((i + 1) & 1) * BUFB;
            int kk = (i + 1) << 5;
            cpasync16(dA + boff, agp + kk, asz);
            cpasync16(dA + boff + 16, agp + kk + 8, asz);
            cpasync16(dB + boff, bgp + kk, 16);
            cpasync16(dB + boff + 16, bgp + kk + 8, 16);
            CP_COMMIT();
            CP_WAIT1();
        } else {
            CP_WAIT0();
        }
        __syncthreads();
        const __half* as = As[i & 1];
        const __half* bs = Bs[i & 1];
        #pragma unroll
        for (int k0 = 0; k0 < 32; k0 += 16) {
            uint32_t af[2][4];
            #pragma unroll
            for (int mt = 0; mt < 2; mt++) {
                int m0 = warpM * 32 + mt * 16 + g;
                const uint32_t* p0 = (const uint32_t*)&as[m0 * RS + k0 + 2 * t4];
                const uint32_t* p1 = (const uint32_t*)&as[(m0 + 8) * RS + k0 + 2 * t4];
                af[mt][0] = p0[0];
                af[mt][1] = p1[0];
                af[mt][2] = p0[4];
                af[mt][3] = p1[4];
            }
            uint32_t bf[8][2];
            #pragma unroll
            for (int nt = 0; nt < 8; nt++) {
                int n0 = warpN * 64 + nt * 8 + g;
                const uint32_t* p = (const uint32_t*)&bs[n0 * RS + k0 + 2 * t4];
                bf[nt][0] = p[0];
                bf[nt][1] = p[4];
            }
            #pragma unroll
            for (int mt = 0; mt < 2; mt++)
                #pragma unroll
                for (int nt = 0; nt < 8; nt++)
                    mma_f16(acc[mt][nt][0], acc[mt][nt][1], acc[mt][nt][2], acc[mt][nt][3],
                            af[mt][0], af[mt][1], af[mt][2], af[mt][3],
                            bf[nt][0], bf[nt][1]);
        }
        __syncthreads();
    }

    #pragma unroll
    for (int mt = 0; mt < 2; mt++) {
        int row0 = bm + warpM * 32 + mt * 16 + g;
        #pragma unroll
        for (int half_ = 0; half_ < 2; half_++) {
            int row = row0 + half_ * 8;
            if (row >= Nn) continue;
            #pragma unroll
            for (int nt = 0; nt < 8; nt++) {
                int col = bn + warpN * 64 + nt * 8 + t4 * 2;
                float c0 = acc[mt][nt][half_ * 2];
                float c1 = acc[mt][nt][half_ * 2 + 1];
                if (mode >= 1) {
                    c0 += bias[col];
                    c1 += bias[col + 1];
                }
                if (mode == 1) {
                    c0 = fmaxf(c0, 0.f);
                    c1 = fmaxf(c1, 0.f);
                    *(__half2*)(g_hid + (size_t)row * M + col) = __floats2half2_rn(c0, c1);
                } else {
                    if (mode == 2) {
                        const float* av = add + (size_t)row * M + col;
                        c0 += av[0];
                        c1 += av[1];
                    }
                    *(float2*)(C + (size_t)row * M + col) = make_float2(c0, c1);
                    if (mode == 0) {
                        __half2 hv = __floats2half2_rn(c0, c1);
                        *(__half2*)(g_pA + (size_t)row * M + col) = hv;
                        *(__half2*)(g_f0h + (size_t)row * M + col) = hv;
                    }
                }
            }
        }
    }
}

// ---------------- weight -> half + zero cnt ----------------
__global__ void whalf_kernel(const float* __restrict__ w_ent,
                             const float* __restrict__ w1,
                             const float* __restrict__ w2) {
    int i = blockIdx.x * blockDim.x + threadIdx.x;
    if (i < Dd * Dd) g_hw0[i] = __float2half_rn(w_ent[i]);
    if (i < FF * Dd) g_hw1[i] = __float2half_rn(w1[i]);
    if (i < Dd * FF) g_hw2[i] = __float2half_rn(w2[i]);
    if (i < Nn) g_cnt[i] = 0;
}

// ---------------- LN1: warp per row (fp32 h + half copy) ----------------
__global__ void __launch_bounds__(256) ln1_kernel(const float* __restrict__ x,
                                                  const float* __restrict__ g,
                                                  const float* __restrict__ b) {
    int row = blockIdx.x * 8 + (threadIdx.x >> 5);
    if (row >= Nn) return;
    int lane = threadIdx.x & 31;
    float4 v = ((const float4*)(x + (size_t)row * Dd))[lane];
    float s  = v.x + v.y + v.z + v.w;
    float sq = v.x * v.x + v.y * v.y + v.z * v.z + v.w * v.w;
    #pragma unroll
    for (int o = 16; o; o >>= 1) {
        s  += __shfl_xor_sync(0xffffffffu, s, o);
        sq += __shfl_xor_sync(0xffffffffu, sq, o);
    }
    float mu  = s * (1.0f / Dd);
    float var = sq * (1.0f / Dd) - mu * mu;
    float inv = rsqrtf(var + 1e-5f);
    float4 gg = ((const float4*)g)[lane];
    float4 bb = ((const float4*)b)[lane];
    float4 o4;
    o4.x = (v.x - mu) * inv * gg.x + bb.x;
    o4.y = (v.y - mu) * inv * gg.y + bb.y;
    o4.z = (v.z - mu) * inv * gg.z + bb.z;
    o4.w = (v.w - mu) * inv * gg.w + bb.w;
    ((float4*)(g_h + (size_t)row * Dd))[lane] = o4;
    __half2* hp = (__half2*)(g_hA + (size_t)row * Dd);
    hp[lane * 2]     = __floats2half2_rn(o4.x, o4.y);
    hp[lane * 2 + 1] = __floats2half2_rn(o4.z, o4.w);
}

// ---------------- eh/et: one thread per (n, h) ----------------
__global__ void __launch_bounds__(256) ehet_kernel(const float* __restrict__ ah,
                                                   const float* __restrict__ at) {
    int i = blockIdx.x * blockDim.x + threadIdx.x;
    if (i >= Nn * Hh) return;
    int h = i & 7;
    const float4* f = (const float4*)(g_feat0 + (size_t)i * 16);
    const float4* wh = (const float4*)(ah + h * 16);
    const float4* wt = (const float4*)(at + h * 16);
    float s1 = 0.f, s2 = 0.f;
    #pragma unroll
    for (int j = 0; j < 4; j++) {
        float4 fv = f[j];
        float4 w1 = wh[j];
        float4 w2 = wt[j];
        s1 += fv.x * w1.x + fv.y * w1.y + fv.z * w1.z + fv.w * w1.w;
        s2 += fv.x * w2.x + fv.y * w2.y + fv.z * w2.z + fv.w * w2.w;
    }
    g_eh[i] = s1;
    g_et[i] = s2;
}

// ---------------- CSR build ----------------
__global__ void hist_kernel(const int* __restrict__ dst) {
    int e = blockIdx.x * blockDim.x + threadIdx.x;
    if (e < Ee) atomicAdd(&g_cnt[dst[e]], 1);
}
__global__ void scan1_kernel() {
    __shared__ int sh[1024];
    int tid = threadIdx.x;
    int i = blockIdx.x * 1024 + tid;
    int v = (i < Nn) ? g_cnt[i] : 0;
    sh[tid] = v;
    __syncthreads();
    for (int off = 1; off < 1024; off <<= 1) {
        int t = (tid >= off) ? sh[tid - off] : 0;
        __syncthreads();
        sh[tid] += t;
        __syncthreads();
    }
    if (i < Nn) g_rowptr[i] = sh[tid] - v;
    if (tid == 1023) g_bsum[blockIdx.x] = sh[1023];
}
__global__ void scan2_kernel(int nb) {
    __shared__ int sh[128];
    int tid = threadIdx.x;
    int v = (tid < nb) ? g_bsum[tid] : 0;
    sh[tid] = v;
    __syncthreads();
    for (int off = 1; off < 128; off <<= 1) {
        int t = (tid >= off) ? sh[tid - off] : 0;
        __syncthreads();
        sh[tid] += t;
        __syncthreads();
    }
    if (tid < nb) g_bsum[tid] = sh[tid] - v;
}
__global__ void scan3_kernel() {
    int i = blockIdx.x * 1024 + threadIdx.x;
    if (i < Nn) {
        int r = g_rowptr[i] + g_bsum[blockIdx.x];
        g_rowptr[i] = r;
        g_wptr[i] = r;
    }
    if (i == 0) g_rowptr[Nn] = Ee;
}
__global__ void fill_kernel(const int* __restrict__ src, const int* __restrict__ dst) {
    int e = blockIdx.x * blockDim.x + threadIdx.x;
    if (e < Ee) {
        int p = atomicAdd(&g_wptr[dst[e]], 1);
        g_srccsr[p] = src[e];
    }
}

// ---------------- edge softmax: ONE gather pass ----------------
// writes UNNORMALIZED exp to g_ach; stores 1/sum per (n,h) for use in hops
__global__ void __launch_bounds__(256) softmax_kernel() {
    int n = blockIdx.x * 8 + (threadIdx.x >> 5);
    if (n >= Nn) return;
    int lane = threadIdx.x & 31;
    int h = lane & 7;
    int sub = lane >> 3;
    int r0 = g_rowptr[n], r1 = g_rowptr[n + 1];
    float myet = g_et[n * Hh + h];

    float sum = 0.f;
    #pragma unroll 4
    for (int p = r0 + sub; p < r1; p += 4) {
        int s = g_srccsr[p];
        float v = g_eh[s * Hh + h] + myet;
        v = v > 0.f ? v : 0.2f * v;
        float e = expf(v);
        g_ach[(size_t)p * Hh + h] = __float2half(e);
        sum += e;
    }
    sum += __shfl_xor_sync(0xffffffffu, sum, 8);
    sum += __shfl_xor_sync(0xffffffffu, sum, 16);
    if (lane < 8) g_invs[n * Hh + h] = 1.0f / sum;
}

// ---------------- one propagation hop: HALF-WARP (16 lanes) per node ----------------
// w = unnormalized_exp * invs[n,h]
__global__ void __launch_bounds__(256) hop_kernel(int ini, int outi) {
    int n = blockIdx.x * 16 + (threadIdx.x >> 4);
    if (n >= Nn) return;
    const __half* __restrict__ fin = hbuf(ini);
    int l = threadIdx.x & 15;
    int h = l >> 1;
    int r0 = g_rowptr[n], r1 = g_rowptr[n + 1];
    float inv = g_invs[n * Hh + h];
    float acc[8] = {0.f, 0.f, 0.f, 0.f, 0.f, 0.f, 0.f, 0.f};
    #pragma unroll 4
    for (int p = r0; p < r1; p++) {
        int s = g_srccsr[p];
        float w = __half2float(g_ach[(size_t)p * Hh + h]);
        uint4 rv = *(const uint4*)(fin + (size_t)s * Dd + l * 8);
        const __half2* hh = (const __half2*)&rv;
        #pragma unroll
        for (int j = 0; j < 4; j++) {
            float2 f = __half22float2(hh[j]);
            acc[2 * j]     += w * f.x;
            acc[2 * j + 1] += w * f.y;
        }
    }
    float sc = 0.85f * inv;
    uint4 f0v = *(const uint4*)(g_f0h + (size_t)n * Dd + l * 8);
    const __half2* fh = (const __half2*)&f0v;
    __half2 ov[4];
    #pragma unroll
    for (int j = 0; j < 4; j++) {
        float2 f = __half22float2(fh[j]);
        ov[j] = __floats2half2_rn(sc * acc[2 * j] + 0.15f * f.x,
                                  sc * acc[2 * j + 1] + 0.15f * f.y);
    }
    *(uint4*)(hbufw(outi) + (size_t)n * Dd + l * 8) = *(uint4*)ov;
}

// ---------------- final hop fused with rst + LN2 (half-warp per node) ----------------
__global__ void __launch_bounds__(256) hop_final_ln2_kernel(const float* __restrict__ g,
                                                            const float* __restrict__ b) {
    int n = blockIdx.x * 16 + (threadIdx.x >> 4);
    if (n >= Nn) return;
    const __half* __restrict__ fin = g_pB;
    int l = threadIdx.x & 15;
    int h = l >> 1;
    int r0 = g_rowptr[n], r1 = g_rowptr[n + 1];
    float inv0 = g_invs[n * Hh + h];
    float acc[8] = {0.f, 0.f, 0.f, 0.f, 0.f, 0.f, 0.f, 0.f};
    #pragma unroll 4
    for (int p = r0; p < r1; p++) {
        int s = g_srccsr[p];
        float w = __half2float(g_ach[(size_t)p * Hh + h]);
        uint4 rv = *(const uint4*)(fin + (size_t)s * Dd + l * 8);
        const __half2* hh = (const __half2*)&rv;
        #pragma unroll
        for (int j = 0; j < 4; j++) {
            float2 f = __half22float2(hh[j]);
            acc[2 * j]     += w * f.x;
            acc[2 * j + 1] += w * f.y;
        }
    }
    float sc = 0.85f * inv0;
    float* f0p = g_feat0 + (size_t)n * Dd + l * 8;
    const float* hp4 = g_h + (size_t)n * Dd + l * 8;
    float4 f0a = *(const float4*)f0p;
    float4 f0b = *(const float4*)(f0p + 4);
    float4 h4a = *(const float4*)hp4;
    float4 h4b = *(const float4*)(hp4 + 4);
    float v[8];
    v[0] = sc * acc[0] + 0.15f * f0a.x + h4a.x;
    v[1] = sc * acc[1] + 0.15f * f0a.y + h4a.y;
    v[2] = sc * acc[2] + 0.15f * f0a.z + h4a.z;
    v[3] = sc * acc[3] + 0.15f * f0a.w + h4a.w;
    v[4] = sc * acc[4] + 0.15f * f0b.x + h4b.x;
    v[5] = sc * acc[5] + 0.15f * f0b.y + h4b.y;
    v[6] = sc * acc[6] + 0.15f * f0b.z + h4b.z;
    v[7] = sc * acc[7] + 0.15f * f0b.w + h4b.w;
    *(float4*)f0p       = make_float4(v[0], v[1], v[2], v[3]);   // rst
    *(float4*)(f0p + 4) = make_float4(v[4], v[5], v[6], v[7]);

    float s = 0.f, sq = 0.f;
    #pragma unroll
    for (int j = 0; j < 8; j++) {
        s += v[j];
        sq += v[j] * v[j];
    }
    #pragma unroll
    for (int o = 8; o; o >>= 1) {
        s  += __shfl_xor_sync(0xffffffffu, s, o);
        sq += __shfl_xor_sync(0xffffffffu, sq, o);
    }
    float mu  = s * (1.0f / Dd);
    float var = sq * (1.0f / Dd) - mu * mu;
    float inv = rsqrtf(var + 1e-5f);
    float4 gga = *(const float4*)(g + l * 8);
    float4 ggb = *(const float4*)(g + l * 8 + 4);
    float4 bba = *(const float4*)(b + l * 8);
    float4 bbb = *(const float4*)(b + l * 8 + 4);
    float gg[8] = {gga.x, gga.y, gga.z, gga.w, ggb.x, ggb.y, ggb.z, ggb.w};
    float bb[8] = {bba.x, bba.y, bba.z, bba.w, bbb.x, bbb.y, bbb.z, bbb.w};
    __half2 ov[4];
    #pragma unroll
    for (int j = 0; j < 4; j++) {
        float o0 = (v[2 * j]     - mu) * inv * gg[2 * j]     + bb[2 * j];
        float o1 = (v[2 * j + 1] - mu) * inv * gg[2 * j + 1] + bb[2 * j + 1];
        ov[j] = __floats2half2_rn(o0, o1);
    }
    *(uint4*)(g_xh + (size_t)n * Dd + l * 8) = *(uint4*)ov;
}

// ---------------- launch ----------------
extern "C" void kernel_launch(void* const* d_in, const int* in_sizes, int n_in,
                              void* d_out, int out_size) {
    const float* ent = (const float*)d_in[0];
    const int*   src = (const int*)d_in[1];
    const int*   dst = (const int*)d_in[2];
    const float* Went = (const float*)d_in[3];
    const float* ah  = (const float*)d_in[4];
    const float* at  = (const float*)d_in[5];
    const float* ln1g = (const float*)d_in[6];
    const float* ln1b = (const float*)d_in[7];
    const float* ln2g = (const float*)d_in[8];
    const float* ln2b = (const float*)d_in[9];
    const float* w1  = (const float*)d_in[10];
    const float* b1  = (const float*)d_in[11];
    const float* w2  = (const float*)d_in[12];
    const float* b2  = (const float*)d_in[13];
    float* out = (float*)d_out;

    const int NWARP_GRID = (Nn + 7) / 8;          // 12500
    const int NHALF_GRID = (Nn + 15) / 16;        // 6250
    const int ROWTILES = (Nn + 127) / 128;        // 782

    whalf_kernel<<<(Nn + 255) / 256, 256>>>(Went, w1, w2);   // also zeroes g_cnt
    ln1_kernel<<<NWARP_GRID, 256>>>(ent, ln1g, ln1b);
    hist_kernel<<<(Ee + 255) / 256, 256>>>(dst);
    // feat0(fp32) + half copies -> g_pA, g_f0h
    hgemm_kernel<<<dim3(1, ROWTILES), 256>>>(0, 3, nullptr, -1, 1, nullptr, 128, 128, 0);
    scan1_kernel<<<(Nn + 1023) / 1024, 1024>>>();
    scan2_kernel<<<1, 128>>>((Nn + 1023) / 1024);
    scan3_kernel<<<(Nn + 1023) / 1024, 1024>>>();
    fill_kernel<<<(Ee + 255) / 256, 256>>>(src, dst);
    ehet_kernel<<<(Nn * Hh + 255) / 256, 256>>>(ah, at);

    softmax_kernel<<<NWARP_GRID, 256>>>();

    hop_kernel<<<NHALF_GRID, 256>>>(6, 7);   // pA -> pB
    hop_kernel<<<NHALF_GRID, 256>>>(7, 6);
    hop_kernel<<<NHALF_GRID, 256>>>(6, 7);
    hop_kernel<<<NHALF_GRID, 256>>>(7, 6);
    hop_kernel<<<NHALF_GRID, 256>>>(6, 7);   // 5th hop -> pB
    hop_final_ln2_kernel<<<NHALF_GRID, 256>>>(ln2g, ln2b);

    // hidden = half(relu(x @ w1^T + b1))
    hgemm_kernel<<<dim3(4, ROWTILES), 256>>>(1, 4, b1, -1, -1, nullptr, 512, 128, 1);
    // out = hidden @ w2^T + b2 + rst
    hgemm_kernel<<<dim3(1, ROWTILES), 256>>>(2, 5, b2, 1, -1, out, 128, 512, 2);
}

// round 16
// speedup vs baseline: 1.0029x; 1.0029x over previous
#include <cuda_runtime.h>
#include <cuda_fp16.h>
#include <cstdint>

#define Nn 100000
#define Ee 1600000
#define Dd 128
#define Hh 8
#define FF 512

// ---------------- scratch (device globals; no allocs allowed) ----------------
__device__ float g_h[Nn * Dd];        // LN1 output (fp32, for rst)
__device__ float g_feat0[Nn * Dd];    // GEMM1 out (fp32); later rst
__device__ float g_eh[Nn * Hh];
__device__ float g_et[Nn * Hh];
__device__ float g_invs[Nn * Hh];     // per-(node,head) 1/sum(exp)
__device__ int   g_srccsr[Ee];        // src node per CSR slot
__device__ int   g_cnt[Nn];
__device__ int   g_rowptr[Nn + 1];
__device__ int   g_wptr[Nn];
__device__ int   g_bsum[128];
// half-precision operands
__device__ __align__(256) __half g_ach[Ee * Hh];   // UNNORMALIZED exp(e) (half)
__device__ __align__(256) __half g_hA[Nn * Dd];    // half(h)  (GEMM1 A)
__device__ __align__(256) __half g_xh[Nn * Dd];    // half(x)  (FFN1 A)
__device__ __align__(256) __half g_hid[Nn * FF];   // half(hidden) (FFN2 A)
__device__ __align__(256) __half g_f0h[Nn * Dd];   // half(feat0) residual
__device__ __align__(256) __half g_hw0[Dd * Dd];
__device__ __align__(256) __half g_hw1[FF * Dd];
__device__ __align__(256) __half g_hw2[Dd * FF];
__device__ __align__(256) __half g_pA[Nn * Dd];    // hop ping (half)
__device__ __align__(256) __half g_pB[Nn * Dd];    // hop pong (half)

__device__ __forceinline__ float* gbuf(int i) {
    switch (i) {
        case 0: return g_h;
        case 1: return g_feat0;
    }
    return nullptr;
}
__device__ __forceinline__ const __half* hbuf(int i) {
    switch (i) {
        case 0: return g_hA;
        case 1: return g_xh;
        case 2: return g_hid;
        case 3: return g_hw0;
        case 4: return g_hw1;
        case 5: return g_hw2;
        case 6: return g_pA;
        case 7: return g_pB;
    }
    return nullptr;
}
__device__ __forceinline__ __half* hbufw(int i) {
    switch (i) {
        case 6: return g_pA;
        case 7: return g_pB;
    }
    return nullptr;
}

__device__ __forceinline__ void mma_f16(float& c0, float& c1, float& c2, float& c3,
                                        uint32_t a0, uint32_t a1, uint32_t a2, uint32_t a3,
                                        uint32_t b0, uint32_t b1) {
    asm volatile(
        "mma.sync.aligned.m16n8k16.row.col.f32.f16.f16.f32 "
        "{%0,%1,%2,%3}, {%4,%5,%6,%7}, {%8,%9}, {%0,%1,%2,%3};"
        : "+f"(c0), "+f"(c1), "+f"(c2), "+f"(c3)
        : "r"(a0), "r"(a1), "r"(a2), "r"(a3), "r"(b0), "r"(b1));
}

__device__ __forceinline__ void ldsm4(uint32_t& r0, uint32_t& r1, uint32_t& r2, uint32_t& r3,
                                      uint32_t addr) {
    asm volatile("ldmatrix.sync.aligned.m8n8.x4.shared.b16 {%0,%1,%2,%3}, [%4];"
                 : "=r"(r0), "=r"(r1), "=r"(r2), "=r"(r3) : "r"(addr));
}

__device__ __forceinline__ void cpasync16(uint32_t s, const void* g, int sz) {
    asm volatile("cp.async.cg.shared.global [%0], [%1], 16, %2;"
                 :: "r"(s), "l"(g), "r"(sz) : "memory");
}
#define CP_COMMIT() asm volatile("cp.async.commit_group;" ::: "memory")
#define CP_WAIT1() asm volatile("cp.async.wait_group 1;" ::: "memory")
#define CP_WAIT0() asm volatile("cp.async.wait_group 0;" ::: "memory")

#define RS 40   // smem row stride in halves (80 B: 16B-aligned, bank-spread, LDSM conflict-free)

// ---------------- fp16 mma GEMM + cp.async double buffer + ldmatrix ----------------
// mode 0: fp32 C + half copies to g_pA/g_f0h   mode 1: half(relu(x+bias)) -> g_hid
// mode 2: fp32 x + bias + add
__global__ void __launch_bounds__(256, 2) hgemm_kernel(int Ai, int Bi,
                                                       const float* __restrict__ bias,
                                                       int Addi, int Ci, float* __restrict__ Cext,
                                                       int M, int K, int mode) {
    __shared__ __half As[2][128 * RS];
    __shared__ __half Bs[2][128 * RS];
    const __half* A = hbuf(Ai);
    const __half* B = hbuf(Bi);
    float* C = (Ci >= 0) ? gbuf(Ci) : Cext;
    const float* add = (Addi >= 0) ? gbuf(Addi) : nullptr;

    int bm = blockIdx.y * 128;
    int bn = blockIdx.x * 128;
    int tid = threadIdx.x;
    int wid = tid >> 5, lane = tid & 31;
    int g = lane >> 2, t4 = lane & 3;
    int warpM = wid & 3, warpN = wid >> 2;

    float acc[2][8][4];
    #pragma unroll
    for (int i = 0; i < 2; i++)
        #pragma unroll
        for (int j = 0; j < 8; j++)
            #pragma unroll
            for (int q = 0; q < 4; q++) acc[i][j][q] = 0.0f;

    int crow = tid >> 1;
    int cch = (tid & 1) * 2;
    bool aval = (bm + crow) < Nn;
    const __half* agp = A + (size_t)(aval ? (bm + crow) : 0) * K + cch * 8;
    const __half* bgp = B + (size_t)(bn + crow) * K + cch * 8;
    int asz = aval ? 16 : 0;

    uint32_t sA = (uint32_t)__cvta_generic_to_shared(As);
    uint32_t sB = (uint32_t)__cvta_generic_to_shared(Bs);
    uint32_t dA = sA + (uint32_t)(crow * RS + cch * 8) * 2u;
    uint32_t dB = sB + (uint32_t)(crow * RS + cch * 8) * 2u;
    const uint32_t BUFB = 128 * RS * 2;

    // ldmatrix per-lane address offsets (bytes)
    // A (per mt tile, 16x16 = 4 8x8 mats): lanes 0-7 rows0-7@k0, 8-15 rows8-15@k0,
    //                                      16-23 rows0-7@k8, 24-31 rows8-15@k8
    int a_r = (lane & 7) + ((lane >> 3) & 1) * 8;
    int a_k = (lane >> 4) * 8;
    uint32_t aoff0 = (uint32_t)((warpM * 32 + a_r) * RS + a_k) * 2u;
    uint32_t aoff1 = aoff0 + 16u * RS * 2u;
    // B (per np pair of nt tiles): lanes 0-7 n0-7@k0, 8-15 n0-7@k8,
    //                              16-23 n8-15@k0, 24-31 n8-15@k8
    int b_r = ((lane >> 4) & 1) * 8 + (lane & 7);
    int b_k = ((lane >> 3) & 1) * 8;
    uint32_t boffs[4];
    #pragma unroll
    for (int np = 0; np < 4; np++)
        boffs[np] = (uint32_t)((warpN * 64 + np * 16 + b_r) * RS + b_k) * 2u;

    const int nit = K >> 5;
    {
        cpasync16(dA, agp, asz);
        cpasync16(dA + 16, agp + 8, asz);
        cpasync16(dB, bgp, 16);
        cpasync16(dB + 16, bgp + 8, 16);
        CP_COMMIT();
    }

    for (int i = 0; i < nit; i++) {
        if (i + 1 < nit) {
            uint32_t boff = ((i + 1) & 1) * BUFB;
            int kk = (i + 1) << 5;
            cpasync16(dA + boff, agp + kk, asz);
            cpasync16(dA + boff + 16, agp + kk + 8, asz);
            cpasync16(dB + boff, bgp + kk, 16);
            cpasync16(dB + boff + 16, bgp + kk + 8, 16);
            CP_COMMIT();
            CP_WAIT1();
        } else {
            CP_WAIT0();
        }
        __syncthreads();
        uint32_t abase = sA + (i & 1) * BUFB;
        uint32_t bbase = sB + (i & 1) * BUFB;
        #pragma unroll
        for (int k0 = 0; k0 < 32; k0 += 16) {
            uint32_t kb = (uint32_t)k0 * 2u;
            uint32_t af[2][4];
            ldsm4(af[0][0], af[0][1], af[0][2], af[0][3], abase + aoff0 + kb);
            ldsm4(af[1][0], af[1][1], af[1][2], af[1][3], abase + aoff1 + kb);
            uint32_t bf[8][2];
            #pragma unroll
            for (int np = 0; np < 4; np++)
                ldsm4(bf[2 * np][0], bf[2 * np][1], bf[2 * np + 1][0], bf[2 * np + 1][1],
                      bbase + boffs[np] + kb);
            #pragma unroll
            for (int mt = 0; mt < 2; mt++)
                #pragma unroll
                for (int nt = 0; nt < 8; nt++)
                    mma_f16(acc[mt][nt][0], acc[mt][nt][1], acc[mt][nt][2], acc[mt][nt][3],
                            af[mt][0], af[mt][1], af[mt][2], af[mt][3],
                            bf[nt][0], bf[nt][1]);
        }
        __syncthreads();
    }

    #pragma unroll
    for (int mt = 0; mt < 2; mt++) {
        int row0 = bm + warpM * 32 + mt * 16 + g;
        #pragma unroll
        for (int half_ = 0; half_ < 2; half_++) {
            int row = row0 + half_ * 8;
            if (row >= Nn) continue;
            #pragma unroll
            for (int nt = 0; nt < 8; nt++) {
                int col = bn + warpN * 64 + nt * 8 + t4 * 2;
                float c0 = acc[mt][nt][half_ * 2];
                float c1 = acc[mt][nt][half_ * 2 + 1];
                if (mode >= 1) {
                    c0 += bias[col];
                    c1 += bias[col + 1];
                }
                if (mode == 1) {
                    c0 = fmaxf(c0, 0.f);
                    c1 = fmaxf(c1, 0.f);
                    *(__half2*)(g_hid + (size_t)row * M + col) = __floats2half2_rn(c0, c1);
                } else {
                    if (mode == 2) {
                        const float* av = add + (size_t)row * M + col;
                        c0 += av[0];
                        c1 += av[1];
                    }
                    *(float2*)(C + (size_t)row * M + col) = make_float2(c0, c1);
                    if (mode == 0) {
                        __half2 hv = __floats2half2_rn(c0, c1);
                        *(__half2*)(g_pA + (size_t)row * M + col) = hv;
                        *(__half2*)(g_f0h + (size_t)row * M + col) = hv;
                    }
                }
            }
        }
    }
}

// ---------------- weight -> half + zero cnt ----------------
__global__ void whalf_kernel(const float* __restrict__ w_ent,
                             const float* __restrict__ w1,
                             const float* __restrict__ w2) {
    int i = blockIdx.x * blockDim.x + threadIdx.x;
    if (i < Dd * Dd) g_hw0[i] = __float2half_rn(w_ent[i]);
    if (i < FF * Dd) g_hw1[i] = __float2half_rn(w1[i]);
    if (i < Dd * FF) g_hw2[i] = __float2half_rn(w2[i]);
    if (i < Nn) g_cnt[i] = 0;
}

// ---------------- LN1: warp per row (fp32 h + half copy) ----------------
__global__ void __launch_bounds__(256) ln1_kernel(const float* __restrict__ x,
                                                  const float* __restrict__ g,
                                                  const float* __restrict__ b) {
    int row = blockIdx.x * 8 + (threadIdx.x >> 5);
    if (row >= Nn) return;
    int lane = threadIdx.x & 31;
    float4 v = ((const float4*)(x + (size_t)row * Dd))[lane];
    float s  = v.x + v.y + v.z + v.w;
    float sq = v.x * v.x + v.y * v.y + v.z * v.z + v.w * v.w;
    #pragma unroll
    for (int o = 16; o; o >>= 1) {
        s  += __shfl_xor_sync(0xffffffffu, s, o);
        sq += __shfl_xor_sync(0xffffffffu, sq, o);
    }
    float mu  = s * (1.0f / Dd);
    float var = sq * (1.0f / Dd) - mu * mu;
    float inv = rsqrtf(var + 1e-5f);
    float4 gg = ((const float4*)g)[lane];
    float4 bb = ((const float4*)b)[lane];
    float4 o4;
    o4.x = (v.x - mu) * inv * gg.x + bb.x;
    o4.y = (v.y - mu) * inv * gg.y + bb.y;
    o4.z = (v.z - mu) * inv * gg.z + bb.z;
    o4.w = (v.w - mu) * inv * gg.w + bb.w;
    ((float4*)(g_h + (size_t)row * Dd))[lane] = o4;
    __half2* hp = (__half2*)(g_hA + (size_t)row * Dd);
    hp[lane * 2]     = __floats2half2_rn(o4.x, o4.y);
    hp[lane * 2 + 1] = __floats2half2_rn(o4.z, o4.w);
}

// ---------------- eh/et: one thread per (n, h) ----------------
__global__ void __launch_bounds__(256) ehet_kernel(const float* __restrict__ ah,
                                                   const float* __restrict__ at) {
    int i = blockIdx.x * blockDim.x + threadIdx.x;
    if (i >= Nn * Hh) return;
    int h = i & 7;
    const float4* f = (const float4*)(g_feat0 + (size_t)i * 16);
    const float4* wh = (const float4*)(ah + h * 16);
    const float4* wt = (const float4*)(at + h * 16);
    float s1 = 0.f, s2 = 0.f;
    #pragma unroll
    for (int j = 0; j < 4; j++) {
        float4 fv = f[j];
        float4 w1 = wh[j];
        float4 w2 = wt[j];
        s1 += fv.x * w1.x + fv.y * w1.y + fv.z * w1.z + fv.w * w1.w;
        s2 += fv.x * w2.x + fv.y * w2.y + fv.z * w2.z + fv.w * w2.w;
    }
    g_eh[i] = s1;
    g_et[i] = s2;
}

// ---------------- CSR build ----------------
__global__ void hist_kernel(const int* __restrict__ dst) {
    int e = blockIdx.x * blockDim.x + threadIdx.x;
    if (e < Ee) atomicAdd(&g_cnt[dst[e]], 1);
}
__global__ void scan1_kernel() {
    __shared__ int sh[1024];
    int tid = threadIdx.x;
    int i = blockIdx.x * 1024 + tid;
    int v = (i < Nn) ? g_cnt[i] : 0;
    sh[tid] = v;
    __syncthreads();
    for (int off = 1; off < 1024; off <<= 1) {
        int t = (tid >= off) ? sh[tid - off] : 0;
        __syncthreads();
        sh[tid] += t;
        __syncthreads();
    }
    if (i < Nn) g_rowptr[i] = sh[tid] - v;
    if (tid == 1023) g_bsum[blockIdx.x] = sh[1023];
}
__global__ void scan2_kernel(int nb) {
    __shared__ int sh[128];
    int tid = threadIdx.x;
    int v = (tid < nb) ? g_bsum[tid] : 0;
    sh[tid] = v;
    __syncthreads();
    for (int off = 1; off < 128; off <<= 1) {
        int t = (tid >= off) ? sh[tid - off] : 0;
        __syncthreads();
        sh[tid] += t;
        __syncthreads();
    }
    if (tid < nb) g_bsum[tid] = sh[tid] - v;
}
__global__ void scan3_kernel() {
    int i = blockIdx.x * 1024 + threadIdx.x;
    if (i < Nn) {
        int r = g_rowptr[i] + g_bsum[blockIdx.x];
        g_rowptr[i] = r;
        g_wptr[i] = r;
    }
    if (i == 0) g_rowptr[Nn] = Ee;
}
__global__ void fill_kernel(const int* __restrict__ src, const int* __restrict__ dst) {
    int e = blockIdx.x * blockDim.x + threadIdx.x;
    if (e < Ee) {
        int p = atomicAdd(&g_wptr[dst[e]], 1);
        g_srccsr[p] = src[e];
    }
}

// ---------------- edge softmax: ONE gather pass ----------------
__global__ void __launch_bounds__(256) softmax_kernel() {
    int n = blockIdx.x * 8 + (threadIdx.x >> 5);
    if (n >= Nn) return;
    int lane = threadIdx.x & 31;
    int h = lane & 7;
    int sub = lane >> 3;
    int r0 = g_rowptr[n], r1 = g_rowptr[n + 1];
    float myet = g_et[n * Hh + h];

    float sum = 0.f;
    #pragma unroll 4
    for (int p = r0 + sub; p < r1; p += 4) {
        int s = g_srccsr[p];
        float v = g_eh[s * Hh + h] + myet;
        v = v > 0.f ? v : 0.2f * v;
        float e = expf(v);
        g_ach[(size_t)p * Hh + h] = __float2half(e);
        sum += e;
    }
    sum += __shfl_xor_sync(0xffffffffu, sum, 8);
    sum += __shfl_xor_sync(0xffffffffu, sum, 16);
    if (lane < 8) g_invs[n * Hh + h] = 1.0f / sum;
}

// ---------------- one propagation hop: HALF-WARP (16 lanes) per node ----------------
__global__ void __launch_bounds__(256) hop_kernel(int ini, int outi) {
    int n = blockIdx.x * 16 + (threadIdx.x >> 4);
    if (n >= Nn) return;
    const __half* __restrict__ fin = hbuf(ini);
    int l = threadIdx.x & 15;
    int h = l >> 1;
    int r0 = g_rowptr[n], r1 = g_rowptr[n + 1];
    float inv = g_invs[n * Hh + h];
    float acc[8] = {0.f, 0.f, 0.f, 0.f, 0.f, 0.f, 0.f, 0.f};
    #pragma unroll 4
    for (int p = r0; p < r1; p++) {
        int s = g_srccsr[p];
        float w = __half2float(g_ach[(size_t)p * Hh + h]);
        uint4 rv = *(const uint4*)(fin + (size_t)s * Dd + l * 8);
        const __half2* hh = (const __half2*)&rv;
        #pragma unroll
        for (int j = 0; j < 4; j++) {
            float2 f = __half22float2(hh[j]);
            acc[2 * j]     += w * f.x;
            acc[2 * j + 1] += w * f.y;
        }
    }
    float sc = 0.85f * inv;
    uint4 f0v = *(const uint4*)(g_f0h + (size_t)n * Dd + l * 8);
    const __half2* fh = (const __half2*)&f0v;
    __half2 ov[4];
    #pragma unroll
    for (int j = 0; j < 4; j++) {
        float2 f = __half22float2(fh[j]);
        ov[j] = __floats2half2_rn(sc * acc[2 * j] + 0.15f * f.x,
                                  sc * acc[2 * j + 1] + 0.15f * f.y);
    }
    *(uint4*)(hbufw(outi) + (size_t)n * Dd + l * 8) = *(uint4*)ov;
}

// ---------------- final hop fused with rst + LN2 (half-warp per node) ----------------
__global__ void __launch_bounds__(256) hop_final_ln2_kernel(const float* __restrict__ g,
                                                            const float* __restrict__ b) {
    int n = blockIdx.x * 16 + (threadIdx.x >> 4);
    if (n >= Nn) return;
    const __half* __restrict__ fin = g_pB;
    int l = threadIdx.x & 15;
    int h = l >> 1;
    int r0 = g_rowptr[n], r1 = g_rowptr[n + 1];
    float inv0 = g_invs[n * Hh + h];
    float acc[8] = {0.f, 0.f, 0.f, 0.f, 0.f, 0.f, 0.f, 0.f};
    #pragma unroll 4
    for (int p = r0; p < r1; p++) {
        int s = g_srccsr[p];
        float w = __half2float(g_ach[(size_t)p * Hh + h]);
        uint4 rv = *(const uint4*)(fin + (size_t)s * Dd + l * 8);
        const __half2* hh = (const __half2*)&rv;
        #pragma unroll
        for (int j = 0; j < 4; j++) {
            float2 f = __half22float2(hh[j]);
            acc[2 * j]     += w * f.x;
            acc[2 * j + 1] += w * f.y;
        }
    }
    float sc = 0.85f * inv0;
    float* f0p = g_feat0 + (size_t)n * Dd + l * 8;
    const float* hp4 = g_h + (size_t)n * Dd + l * 8;
    float4 f0a = *(const float4*)f0p;
    float4 f0b = *(const float4*)(f0p + 4);
    float4 h4a = *(const float4*)hp4;
    float4 h4b = *(const float4*)(hp4 + 4);
    float v[8];
    v[0] = sc * acc[0] + 0.15f * f0a.x + h4a.x;
    v[1] = sc * acc[1] + 0.15f * f0a.y + h4a.y;
    v[2] = sc * acc[2] + 0.15f * f0a.z + h4a.z;
    v[3] = sc * acc[3] + 0.15f * f0a.w + h4a.w;
    v[4] = sc * acc[4] + 0.15f * f0b.x + h4b.x;
    v[5] = sc * acc[5] + 0.15f * f0b.y + h4b.y;
    v[6] = sc * acc[6] + 0.15f * f0b.z + h4b.z;
    v[7] = sc * acc[7] + 0.15f * f0b.w + h4b.w;
    *(float4*)f0p       = make_float4(v[0], v[1], v[2], v[3]);   // rst
    *(float4*)(f0p + 4) = make_float4(v[4], v[5], v[6], v[7]);

    float s = 0.f, sq = 0.f;
    #pragma unroll
    for (int j = 0; j < 8; j++) {
        s += v[j];
        sq += v[j] * v[j];
    }
    #pragma unroll
    for (int o = 8; o; o >>= 1) {
        s  += __shfl_xor_sync(0xffffffffu, s, o);
        sq += __shfl_xor_sync(0xffffffffu, sq, o);
    }
    float mu  = s * (1.0f / Dd);
    float var = sq * (1.0f / Dd) - mu * mu;
    float inv = rsqrtf(var + 1e-5f);
    float4 gga = *(const float4*)(g + l * 8);
    float4 ggb = *(const float4*)(g + l * 8 + 4);
    float4 bba = *(const float4*)(b + l * 8);
    float4 bbb = *(const float4*)(b + l * 8 + 4);
    float gg[8] = {gga.x, gga.y, gga.z, gga.w, ggb.x, ggb.y, ggb.z, ggb.w};
    float bb[8] = {bba.x, bba.y, bba.z, bba.w, bbb.x, bbb.y, bbb.z, bbb.w};
    __half2 ov[4];
    #pragma unroll
    for (int j = 0; j < 4; j++) {
        float o0 = (v[2 * j]     - mu) * inv * gg[2 * j]     + bb[2 * j];
        float o1 = (v[2 * j + 1] - mu) * inv * gg[2 * j + 1] + bb[2 * j + 1];
        ov[j] = __floats2half2_rn(o0, o1);
    }
    *(uint4*)(g_xh + (size_t)n * Dd + l * 8) = *(uint4*)ov;
}

// ---------------- launch ----------------
extern "C" void kernel_launch(void* const* d_in, const int* in_sizes, int n_in,
                              void* d_out, int out_size) {
    const float* ent = (const float*)d_in[0];
    const int*   src = (const int*)d_in[1];
    const int*   dst = (const int*)d_in[2];
    const float* Went = (const float*)d_in[3];
    const float* ah  = (const float*)d_in[4];
    const float* at  = (const float*)d_in[5];
    const float* ln1g = (const float*)d_in[6];
    const float* ln1b = (const float*)d_in[7];
    const float* ln2g = (const float*)d_in[8];
    const float* ln2b = (const float*)d_in[9];
    const float* w1  = (const float*)d_in[10];
    const float* b1  = (const float*)d_in[11];
    const float* w2  = (const float*)d_in[12];
    const float* b2  = (const float*)d_in[13];
    float* out = (float*)d_out;

    const int NWARP_GRID = (Nn + 7) / 8;          // 12500
    const int NHALF_GRID = (Nn + 15) / 16;        // 6250
    const int ROWTILES = (Nn + 127) / 128;        // 782

    whalf_kernel<<<(Nn + 255) / 256, 256>>>(Went, w1, w2);   // also zeroes g_cnt
    ln1_kernel<<<NWARP_GRID, 256>>>(ent, ln1g, ln1b);
    hist_kernel<<<(Ee + 255) / 256, 256>>>(dst);
    // feat0(fp32) + half copies -> g_pA, g_f0h
    hgemm_kernel<<<dim3(1, ROWTILES), 256>>>(0, 3, nullptr, -1, 1, nullptr, 128, 128, 0);
    scan1_kernel<<<(Nn + 1023) / 1024, 1024>>>();
    scan2_kernel<<<1, 128>>>((Nn + 1023) / 1024);
    scan3_kernel<<<(Nn + 1023) / 1024, 1024>>>();
    fill_kernel<<<(Ee + 255) / 256, 256>>>(src, dst);
    ehet_kernel<<<(Nn * Hh + 255) / 256, 256>>>(ah, at);

    softmax_kernel<<<NWARP_GRID, 256>>>();

    hop_kernel<<<NHALF_GRID, 256>>>(6, 7);   // pA -> pB
    hop_kernel<<<NHALF_GRID, 256>>>(7, 6);
    hop_kernel<<<NHALF_GRID, 256>>>(6, 7);
    hop_kernel<<<NHALF_GRID, 256>>>(7, 6);
    hop_kernel<<<NHALF_GRID, 256>>>(6, 7);   // 5th hop -> pB
    hop_final_ln2_kernel<<<NHALF_GRID, 256>>>(ln2g, ln2b);

    // hidden = half(relu(x @ w1^T + b1))
    hgemm_kernel<<<dim3(4, ROWTILES), 256>>>(1, 4, b1, -1, -1, nullptr, 512, 128, 1);
    // out = hidden @ w2^T + b2 + rst
    hgemm_kernel<<<dim3(1, ROWTILES), 256>>>(2, 5, b2, 1, -1, out, 128, 512, 2);
}

// round 17
// speedup vs baseline: 1.0119x; 1.0090x over previous
#include <cuda_runtime.h>
#include <cuda_fp16.h>
#include <cstdint>

#define Nn 100000
#define Ee 1600000
#define Dd 128
#define Hh 8
#define FF 512

// ---------------- scratch (device globals; no allocs allowed) ----------------
__device__ float g_h[Nn * Dd];        // LN1 output (fp32, for rst)
__device__ float g_feat0[Nn * Dd];    // GEMM1 out (fp32); later rst
__device__ float g_eh[Nn * Hh];
__device__ float g_et[Nn * Hh];
__device__ float g_invs[Nn * Hh];     // per-(node,head) 1/sum(exp)
__device__ int   g_srccsr[Ee];        // src node per CSR slot
__device__ int   g_cnt[Nn];
__device__ int   g_rowptr[Nn + 1];
__device__ int   g_wptr[Nn];
__device__ int   g_bsum[128];
// half-precision operands
__device__ __align__(256) __half g_ach[Ee * Hh];   // UNNORMALIZED exp(e) (half)
__device__ __align__(256) __half g_hA[Nn * Dd];    // half(h)  (GEMM1 A)
__device__ __align__(256) __half g_xh[Nn * Dd];    // half(x)  (FFN1 A)
__device__ __align__(256) __half g_hid[Nn * FF];   // half(hidden) (FFN2 A)
__device__ __align__(256) __half g_f0h[Nn * Dd];   // half(feat0) residual
__device__ __align__(256) __half g_hw0[Dd * Dd];
__device__ __align__(256) __half g_hw1[FF * Dd];
__device__ __align__(256) __half g_hw2[Dd * FF];
__device__ __align__(256) __half g_pA[Nn * Dd];    // hop ping (half)
__device__ __align__(256) __half g_pB[Nn * Dd];    // hop pong (half)

__device__ __forceinline__ float* gbuf(int i) {
    switch (i) {
        case 0: return g_h;
        case 1: return g_feat0;
    }
    return nullptr;
}
__device__ __forceinline__ const __half* hbuf(int i) {
    switch (i) {
        case 0: return g_hA;
        case 1: return g_xh;
        case 2: return g_hid;
        case 3: return g_hw0;
        case 4: return g_hw1;
        case 5: return g_hw2;
        case 6: return g_pA;
        case 7: return g_pB;
    }
    return nullptr;
}
__device__ __forceinline__ __half* hbufw(int i) {
    switch (i) {
        case 6: return g_pA;
        case 7: return g_pB;
    }
    return nullptr;
}

__device__ __forceinline__ void mma_f16(float& c0, float& c1, float& c2, float& c3,
                                        uint32_t a0, uint32_t a1, uint32_t a2, uint32_t a3,
                                        uint32_t b0, uint32_t b1) {
    asm volatile(
        "mma.sync.aligned.m16n8k16.row.col.f32.f16.f16.f32 "
        "{%0,%1,%2,%3}, {%4,%5,%6,%7}, {%8,%9}, {%0,%1,%2,%3};"
        : "+f"(c0), "+f"(c1), "+f"(c2), "+f"(c3)
        : "r"(a0), "r"(a1), "r"(a2), "r"(a3), "r"(b0), "r"(b1));
}

__device__ __forceinline__ void ldsm4(uint32_t& r0, uint32_t& r1, uint32_t& r2, uint32_t& r3,
                                      uint32_t addr) {
    asm volatile("ldmatrix.sync.aligned.m8n8.x4.shared.b16 {%0,%1,%2,%3}, [%4];"
                 : "=r"(r0), "=r"(r1), "=r"(r2), "=r"(r3) : "r"(addr));
}

__device__ __forceinline__ void cpasync16(uint32_t s, const void* g, int sz) {
    asm volatile("cp.async.cg.shared.global [%0], [%1], 16, %2;"
                 :: "r"(s), "l"(g), "r"(sz) : "memory");
}
#define CP_COMMIT() asm volatile("cp.async.commit_group;" ::: "memory")
#define CP_WAIT1() asm volatile("cp.async.wait_group 1;" ::: "memory")
#define CP_WAIT0() asm volatile("cp.async.wait_group 0;" ::: "memory")

#define RS 40   // smem row stride in halves (80 B: 16B-aligned, bank-spread, LDSM conflict-free)

// ---------------- fp16 mma GEMM + cp.async double buffer + ldmatrix ----------------
// mode 0: fp32 C + half copies to g_pA/g_f0h   mode 1: half(relu(x+bias)) -> g_hid
// mode 2: fp32 x + bias + add
__global__ void __launch_bounds__(256, 2) hgemm_kernel(int Ai, int Bi,
                                                       const float* __restrict__ bias,
                                                       int Addi, int Ci, float* __restrict__ Cext,
                                                       int M, int K, int mode) {
    __shared__ __half As[2][128 * RS];
    __shared__ __half Bs[2][128 * RS];
    const __half* A = hbuf(Ai);
    const __half* B = hbuf(Bi);
    float* C = (Ci >= 0) ? gbuf(Ci) : Cext;
    const float* add = (Addi >= 0) ? gbuf(Addi) : nullptr;

    int bm = blockIdx.y * 128;
    int bn = blockIdx.x * 128;
    int tid = threadIdx.x;
    int wid = tid >> 5, lane = tid & 31;
    int g = lane >> 2, t4 = lane & 3;
    int warpM = wid & 3, warpN = wid >> 2;

    float acc[2][8][4];
    #pragma unroll
    for (int i = 0; i < 2; i++)
        #pragma unroll
        for (int j = 0; j < 8; j++)
            #pragma unroll
            for (int q = 0; q < 4; q++) acc[i][j][q] = 0.0f;

    int crow = tid >> 1;
    int cch = (tid & 1) * 2;
    bool aval = (bm + crow) < Nn;
    const __half* agp = A + (size_t)(aval ? (bm + crow) : 0) * K + cch * 8;
    const __half* bgp = B + (size_t)(bn + crow) * K + cch * 8;
    int asz = aval ? 16 : 0;

    uint32_t sA = (uint32_t)__cvta_generic_to_shared(As);
    uint32_t sB = (uint32_t)__cvta_generic_to_shared(Bs);
    uint32_t dA = sA + (uint32_t)(crow * RS + cch * 8) * 2u;
    uint32_t dB = sB + (uint32_t)(crow * RS + cch * 8) * 2u;
    const uint32_t BUFB = 128 * RS * 2;

    int a_r = (lane & 7) + ((lane >> 3) & 1) * 8;
    int a_k = (lane >> 4) * 8;
    uint32_t aoff0 = (uint32_t)((warpM * 32 + a_r) * RS + a_k) * 2u;
    uint32_t aoff1 = aoff0 + 16u * RS * 2u;
    int b_r = ((lane >> 4) & 1) * 8 + (lane & 7);
    int b_k = ((lane >> 3) & 1) * 8;
    uint32_t boffs[4];
    #pragma unroll
    for (int np = 0; np < 4; np++)
        boffs[np] = (uint32_t)((warpN * 64 + np * 16 + b_r) * RS + b_k) * 2u;

    const int nit = K >> 5;
    {
        cpasync16(dA, agp, asz);
        cpasync16(dA + 16, agp + 8, asz);
        cpasync16(dB, bgp, 16);
        cpasync16(dB + 16, bgp + 8, 16);
        CP_COMMIT();
    }

    for (int i = 0; i < nit; i++) {
        if (i + 1 < nit) {
            uint32_t boff = ((i + 1) & 1) * BUFB;
            int kk = (i + 1) << 5;
            cpasync16(dA + boff, agp + kk, asz);
            cpasync16(dA + boff + 16, agp + kk + 8, asz);
            cpasync16(dB + boff, bgp + kk, 16);
            cpasync16(dB + boff + 16, bgp + kk + 8, 16);
            CP_COMMIT();
            CP_WAIT1();
        } else {
            CP_WAIT0();
        }
        __syncthreads();
        uint32_t abase = sA + (i & 1) * BUFB;
        uint32_t bbase = sB + (i & 1) * BUFB;
        #pragma unroll
        for (int k0 = 0; k0 < 32; k0 += 16) {
            uint32_t kb = (uint32_t)k0 * 2u;
            uint32_t af[2][4];
            ldsm4(af[0][0], af[0][1], af[0][2], af[0][3], abase + aoff0 + kb);
            ldsm4(af[1][0], af[1][1], af[1][2], af[1][3], abase + aoff1 + kb);
            uint32_t bf[8][2];
            #pragma unroll
            for (int np = 0; np < 4; np++)
                ldsm4(bf[2 * np][0], bf[2 * np][1], bf[2 * np + 1][0], bf[2 * np + 1][1],
                      bbase + boffs[np] + kb);
            #pragma unroll
            for (int mt = 0; mt < 2; mt++)
                #pragma unroll
                for (int nt = 0; nt < 8; nt++)
                    mma_f16(acc[mt][nt][0], acc[mt][nt][1], acc[mt][nt][2], acc[mt][nt][3],
                            af[mt][0], af[mt][1], af[mt][2], af[mt][3],
                            bf[nt][0], bf[nt][1]);
        }
        __syncthreads();
    }

    #pragma unroll
    for (int mt = 0; mt < 2; mt++) {
        int row0 = bm + warpM * 32 + mt * 16 + g;
        #pragma unroll
        for (int half_ = 0; half_ < 2; half_++) {
            int row = row0 + half_ * 8;
            if (row >= Nn) continue;
            #pragma unroll
            for (int nt = 0; nt < 8; nt++) {
                int col = bn + warpN * 64 + nt * 8 + t4 * 2;
                float c0 = acc[mt][nt][half_ * 2];
                float c1 = acc[mt][nt][half_ * 2 + 1];
                if (mode >= 1) {
                    c0 += bias[col];
                    c1 += bias[col + 1];
                }
                if (mode == 1) {
                    c0 = fmaxf(c0, 0.f);
                    c1 = fmaxf(c1, 0.f);
                    *(__half2*)(g_hid + (size_t)row * M + col) = __floats2half2_rn(c0, c1);
                } else {
                    if (mode == 2) {
                        const float* av = add + (size_t)row * M + col;
                        c0 += av[0];
                        c1 += av[1];
                    }
                    *(float2*)(C + (size_t)row * M + col) = make_float2(c0, c1);
                    if (mode == 0) {
                        __half2 hv = __floats2half2_rn(c0, c1);
                        *(__half2*)(g_pA + (size_t)row * M + col) = hv;
                        *(__half2*)(g_f0h + (size_t)row * M + col) = hv;
                    }
                }
            }
        }
    }
}

// ---------------- weight -> half + zero cnt ----------------
__global__ void whalf_kernel(const float* __restrict__ w_ent,
                             const float* __restrict__ w1,
                             const float* __restrict__ w2) {
    int i = blockIdx.x * blockDim.x + threadIdx.x;
    if (i < Dd * Dd) g_hw0[i] = __float2half_rn(w_ent[i]);
    if (i < FF * Dd) g_hw1[i] = __float2half_rn(w1[i]);
    if (i < Dd * FF) g_hw2[i] = __float2half_rn(w2[i]);
    if (i < Nn) g_cnt[i] = 0;
}

// ---------------- LN1: warp per row (fp32 h + half copy) ----------------
__global__ void __launch_bounds__(256) ln1_kernel(const float* __restrict__ x,
                                                  const float* __restrict__ g,
                                                  const float* __restrict__ b) {
    int row = blockIdx.x * 8 + (threadIdx.x >> 5);
    if (row >= Nn) return;
    int lane = threadIdx.x & 31;
    float4 v = ((const float4*)(x + (size_t)row * Dd))[lane];
    float s  = v.x + v.y + v.z + v.w;
    float sq = v.x * v.x + v.y * v.y + v.z * v.z + v.w * v.w;
    #pragma unroll
    for (int o = 16; o; o >>= 1) {
        s  += __shfl_xor_sync(0xffffffffu, s, o);
        sq += __shfl_xor_sync(0xffffffffu, sq, o);
    }
    float mu  = s * (1.0f / Dd);
    float var = sq * (1.0f / Dd) - mu * mu;
    float inv = rsqrtf(var + 1e-5f);
    float4 gg = ((const float4*)g)[lane];
    float4 bb = ((const float4*)b)[lane];
    float4 o4;
    o4.x = (v.x - mu) * inv * gg.x + bb.x;
    o4.y = (v.y - mu) * inv * gg.y + bb.y;
    o4.z = (v.z - mu) * inv * gg.z + bb.z;
    o4.w = (v.w - mu) * inv * gg.w + bb.w;
    ((float4*)(g_h + (size_t)row * Dd))[lane] = o4;
    __half2* hp = (__half2*)(g_hA + (size_t)row * Dd);
    hp[lane * 2]     = __floats2half2_rn(o4.x, o4.y);
    hp[lane * 2 + 1] = __floats2half2_rn(o4.z, o4.w);
}

// ---------------- eh/et: one thread per (n, h); reads HALF feat ----------------
__global__ void __launch_bounds__(256) ehet_kernel(const float* __restrict__ ah,
                                                   const float* __restrict__ at) {
    int i = blockIdx.x * blockDim.x + threadIdx.x;
    if (i >= Nn * Hh) return;
    int h = i & 7;
    const uint4* f = (const uint4*)(g_f0h + (size_t)i * 16);   // 16 halves = 2 uint4
    const float4* wh = (const float4*)(ah + h * 16);
    const float4* wt = (const float4*)(at + h * 16);
    float s1 = 0.f, s2 = 0.f;
    #pragma unroll
    for (int q = 0; q < 2; q++) {
        uint4 fv = f[q];
        const __half2* hh = (const __half2*)&fv;
        #pragma unroll
        for (int j = 0; j < 4; j++) {
            float2 fp = __half22float2(hh[j]);
            int base = q * 8 + j * 2;
            float w1a = ((const float*)wh)[base];
            float w1b = ((const float*)wh)[base + 1];
            float w2a = ((const float*)wt)[base];
            float w2b = ((const float*)wt)[base + 1];
            s1 += fp.x * w1a + fp.y * w1b;
            s2 += fp.x * w2a + fp.y * w2b;
        }
    }
    g_eh[i] = s1;
    g_et[i] = s2;
}

// ---------------- CSR build ----------------
__global__ void hist_kernel(const int* __restrict__ dst) {
    int e = blockIdx.x * blockDim.x + threadIdx.x;
    if (e < Ee) atomicAdd(&g_cnt[dst[e]], 1);
}
__global__ void scan1_kernel() {
    __shared__ int sh[1024];
    int tid = threadIdx.x;
    int i = blockIdx.x * 1024 + tid;
    int v = (i < Nn) ? g_cnt[i] : 0;
    sh[tid] = v;
    __syncthreads();
    for (int off = 1; off < 1024; off <<= 1) {
        int t = (tid >= off) ? sh[tid - off] : 0;
        __syncthreads();
        sh[tid] += t;
        __syncthreads();
    }
    if (i < Nn) g_rowptr[i] = sh[tid] - v;
    if (tid == 1023) g_bsum[blockIdx.x] = sh[1023];
}
__global__ void scan2_kernel(int nb) {
    __shared__ int sh[128];
    int tid = threadIdx.x;
    int v = (tid < nb) ? g_bsum[tid] : 0;
    sh[tid] = v;
    __syncthreads();
    for (int off = 1; off < 128; off <<= 1) {
        int t = (tid >= off) ? sh[tid - off] : 0;
        __syncthreads();
        sh[tid] += t;
        __syncthreads();
    }
    if (tid < nb) g_bsum[tid] = sh[tid] - v;
}
__global__ void scan3_kernel() {
    int i = blockIdx.x * 1024 + threadIdx.x;
    if (i < Nn) {
        int r = g_rowptr[i] + g_bsum[blockIdx.x];
        g_rowptr[i] = r;
        g_wptr[i] = r;
    }
    if (i == 0) g_rowptr[Nn] = Ee;
}
__global__ void fill_kernel(const int* __restrict__ src, const int* __restrict__ dst) {
    int e = blockIdx.x * blockDim.x + threadIdx.x;
    if (e < Ee) {
        int p = atomicAdd(&g_wptr[dst[e]], 1);
        g_srccsr[p] = src[e];
    }
}

// ---------------- edge softmax: ONE gather pass ----------------
__global__ void __launch_bounds__(256) softmax_kernel() {
    int n = blockIdx.x * 8 + (threadIdx.x >> 5);
    if (n >= Nn) return;
    int lane = threadIdx.x & 31;
    int h = lane & 7;
    int sub = lane >> 3;
    int r0 = g_rowptr[n], r1 = g_rowptr[n + 1];
    float myet = g_et[n * Hh + h];

    float sum = 0.f;
    #pragma unroll 4
    for (int p = r0 + sub; p < r1; p += 4) {
        int s = g_srccsr[p];
        float v = g_eh[s * Hh + h] + myet;
        v = v > 0.f ? v : 0.2f * v;
        float e = expf(v);
        g_ach[(size_t)p * Hh + h] = __float2half(e);
        sum += e;
    }
    sum += __shfl_xor_sync(0xffffffffu, sum, 8);
    sum += __shfl_xor_sync(0xffffffffu, sum, 16);
    if (lane < 8) g_invs[n * Hh + h] = 1.0f / sum;
}

// ---------------- one propagation hop: HALF-WARP (16 lanes) per node ----------------
__global__ void __launch_bounds__(256) hop_kernel(int ini, int outi) {
    int n = blockIdx.x * 16 + (threadIdx.x >> 4);
    if (n >= Nn) return;
    const __half* __restrict__ fin = hbuf(ini);
    int l = threadIdx.x & 15;
    int h = l >> 1;
    int r0 = g_rowptr[n], r1 = g_rowptr[n + 1];
    float inv = g_invs[n * Hh + h];
    float acc[8] = {0.f, 0.f, 0.f, 0.f, 0.f, 0.f, 0.f, 0.f};
    #pragma unroll 4
    for (int p = r0; p < r1; p++) {
        int s = g_srccsr[p];
        float w = __half2float(g_ach[(size_t)p * Hh + h]);
        uint4 rv = *(const uint4*)(fin + (size_t)s * Dd + l * 8);
        const __half2* hh = (const __half2*)&rv;
        #pragma unroll
        for (int j = 0; j < 4; j++) {
            float2 f = __half22float2(hh[j]);
            acc[2 * j]     += w * f.x;
            acc[2 * j + 1] += w * f.y;
        }
    }
    float sc = 0.85f * inv;
    uint4 f0v = *(const uint4*)(g_f0h + (size_t)n * Dd + l * 8);
    const __half2* fh = (const __half2*)&f0v;
    __half2 ov[4];
    #pragma unroll
    for (int j = 0; j < 4; j++) {
        float2 f = __half22float2(fh[j]);
        ov[j] = __floats2half2_rn(sc * acc[2 * j] + 0.15f * f.x,
                                  sc * acc[2 * j + 1] + 0.15f * f.y);
    }
    *(uint4*)(hbufw(outi) + (size_t)n * Dd + l * 8) = *(uint4*)ov;
}

// ---------------- final hop fused with rst + LN2 (half-warp per node) ----------------
__global__ void __launch_bounds__(256) hop_final_ln2_kernel(const float* __restrict__ g,
                                                            const float* __restrict__ b) {
    int n = blockIdx.x * 16 + (threadIdx.x >> 4);
    if (n >= Nn) return;
    const __half* __restrict__ fin = g_pB;
    int l = threadIdx.x & 15;
    int h = l >> 1;
    int r0 = g_rowptr[n], r1 = g_rowptr[n + 1];
    float inv0 = g_invs[n * Hh + h];
    float acc[8] = {0.f, 0.f, 0.f, 0.f, 0.f, 0.f, 0.f, 0.f};
    #pragma unroll 4
    for (int p = r0; p < r1; p++) {
        int s = g_srccsr[p];
        float w = __half2float(g_ach[(size_t)p * Hh + h]);
        uint4 rv = *(const uint4*)(fin + (size_t)s * Dd + l * 8);
        const __half2* hh = (const __half2*)&rv;
        #pragma unroll
        for (int j = 0; j < 4; j++) {
            float2 f = __half22float2(hh[j]);
            acc[2 * j]     += w * f.x;
            acc[2 * j + 1] += w * f.y;
        }
    }
    float sc = 0.85f * inv0;
    float* f0p = g_feat0 + (size_t)n * Dd + l * 8;
    const float* hp4 = g_h + (size_t)n * Dd + l * 8;
    float4 f0a = *(const float4*)f0p;
    float4 f0b = *(const float4*)(f0p + 4);
    float4 h4a = *(const float4*)hp4;
    float4 h4b = *(const float4*)(hp4 + 4);
    float v[8];
    v[0] = sc * acc[0] + 0.15f * f0a.x + h4a.x;
    v[1] = sc * acc[1] + 0.15f * f0a.y + h4a.y;
    v[2] = sc * acc[2] + 0.15f * f0a.z + h4a.z;
    v[3] = sc * acc[3] + 0.15f * f0a.w + h4a.w;
    v[4] = sc * acc[4] + 0.15f * f0b.x + h4b.x;
    v[5] = sc * acc[5] + 0.15f * f0b.y + h4b.y;
    v[6] = sc * acc[6] + 0.15f * f0b.z + h4b.z;
    v[7] = sc * acc[7] + 0.15f * f0b.w + h4b.w;
    *(float4*)f0p       = make_float4(v[0], v[1], v[2], v[3]);   // rst
    *(float4*)(f0p + 4) = make_float4(v[4], v[5], v[6], v[7]);

    float s = 0.f, sq = 0.f;
    #pragma unroll
    for (int j = 0; j < 8; j++) {
        s += v[j];
        sq += v[j] * v[j];
    }
    #pragma unroll
    for (int o = 8; o; o >>= 1) {
        s  += __shfl_xor_sync(0xffffffffu, s, o);
        sq += __shfl_xor_sync(0xffffffffu, sq, o);
    }
    float mu  = s * (1.0f / Dd);
    float var = sq * (1.0f / Dd) - mu * mu;
    float inv = rsqrtf(var + 1e-5f);
    float4 gga = *(const float4*)(g + l * 8);
    float4 ggb = *(const float4*)(g + l * 8 + 4);
    float4 bba = *(const float4*)(b + l * 8);
    float4 bbb = *(const float4*)(b + l * 8 + 4);
    float gg[8] = {gga.x, gga.y, gga.z, gga.w, ggb.x, ggb.y, ggb.z, ggb.w};
    float bb[8] = {bba.x, bba.y, bba.z, bba.w, bbb.x, bbb.y, bbb.z, bbb.w};
    __half2 ov[4];
    #pragma unroll
    for (int j = 0; j < 4; j++) {
        float o0 = (v[2 * j]     - mu) * inv * gg[2 * j]     + bb[2 * j];
        float o1 = (v[2 * j + 1] - mu) * inv * gg[2 * j + 1] + bb[2 * j + 1];
        ov[j] = __floats2half2_rn(o0, o1);
    }
    *(uint4*)(g_xh + (size_t)n * Dd + l * 8) = *(uint4*)ov;
}

// ---------------- launch ----------------
extern "C" void kernel_launch(void* const* d_in, const int* in_sizes, int n_in,
                              void* d_out, int out_size) {
    const float* ent = (const float*)d_in[0];
    const int*   src = (const int*)d_in[1];
    const int*   dst = (const int*)d_in[2];
    const float* Went = (const float*)d_in[3];
    const float* ah  = (const float*)d_in[4];
    const float* at  = (const float*)d_in[5];
    const float* ln1g = (const float*)d_in[6];
    const float* ln1b = (const float*)d_in[7];
    const float* ln2g = (const float*)d_in[8];
    const float* ln2b = (const float*)d_in[9];
    const float* w1  = (const float*)d_in[10];
    const float* b1  = (const float*)d_in[11];
    const float* w2  = (const float*)d_in[12];
    const float* b2  = (const float*)d_in[13];
    float* out = (float*)d_out;

    const int NWARP_GRID = (Nn + 7) / 8;          // 12500
    const int NHALF_GRID = (Nn + 15) / 16;        // 6250
    const int ROWTILES = (Nn + 127) / 128;        // 782

    whalf_kernel<<<(Nn + 255) / 256, 256>>>(Went, w1, w2);   // also zeroes g_cnt
    ln1_kernel<<<NWARP_GRID, 256>>>(ent, ln1g, ln1b);
    hist_kernel<<<(Ee + 255) / 256, 256>>>(dst);
    // feat0(fp32) + half copies -> g_pA, g_f0h
    hgemm_kernel<<<dim3(1, ROWTILES), 256>>>(0, 3, nullptr, -1, 1, nullptr, 128, 128, 0);
    scan1_kernel<<<(Nn + 1023) / 1024, 1024>>>();
    scan2_kernel<<<1, 128>>>((Nn + 1023) / 1024);
    scan3_kernel<<<(Nn + 1023) / 1024, 1024>>>();
    fill_kernel<<<(Ee + 255) / 256, 256>>>(src, dst);
    ehet_kernel<<<(Nn * Hh + 255) / 256, 256>>>(ah, at);

    softmax_kernel<<<NWARP_GRID, 256>>>();

    hop_kernel<<<NHALF_GRID, 256>>>(6, 7);   // pA -> pB
    hop_kernel<<<NHALF_GRID, 256>>>(7, 6);
    hop_kernel<<<NHALF_GRID, 256>>>(6, 7);
    hop_kernel<<<NHALF_GRID, 256>>>(7, 6);
    hop_kernel<<<NHALF_GRID, 256>>>(6, 7);   // 5th hop -> pB
    hop_final_ln2_kernel<<<NHALF_GRID, 256>>>(ln2g, ln2b);

    // hidden = half(relu(x @ w1^T + b1))
    hgemm_kernel<<<dim3(4, ROWTILES), 256>>>(1, 4, b1, -1, -1, nullptr, 512, 128, 1);
    // out = hidden @ w2^T + b2 + rst
    hgemm_kernel<<<dim3(1, ROWTILES), 256>>>(2, 5, b2, 1, -1, out, 128, 512, 2);
}